// round 7
// baseline (speedup 1.0000x reference)
#include <cuda_runtime.h>
#include <cuda_fp16.h>
#include <cstdint>

// ===================== problem constants =====================
#define K_DIM 4096
#define N_DIM 16384
#define M_MAX 8192

// ===================== GEMM tiling =====================
#define BM 128
#define BN 256
#define BK 64                      // fp16 elems = 128 bytes = one swizzled row
#define STAGES 3
#define NKT (K_DIM / BK)           // 64
#define THREADS 512                // 16 warps: 2 (M) x 8 (N), warp tile 64x32

#define A_STAGE_BYTES (BM * 128)   // 16384
#define B_STAGE_BYTES (BN * 128)   // 32768

// shared memory layout (relative to 128B-aligned base)
#define OFF_INV  0                 // BN floats
#define OFF_BIAS (BN * 4)          // BN floats
#define OFF_A    (2 * BN * 4)      // 2048, 128B aligned
#define OFF_B    (OFF_A + STAGES * A_STAGE_BYTES)
#define SMEM_USE (OFF_B + STAGES * B_STAGE_BYTES)
#define SMEM_ALLOC (SMEM_USE + 256)

// fp16 scratch (conversion targets) — __device__ globals per allocation rules
__device__ __align__(16) __half g_xh[(size_t)M_MAX * K_DIM];
__device__ __align__(16) __half g_wh[(size_t)N_DIM * K_DIM];

// ===================== PTX helpers =====================
__device__ __forceinline__ uint32_t smem_u32(const void* p) {
    uint32_t a;
    asm("{ .reg .u64 t; cvta.to.shared.u64 t, %1; cvt.u32.u64 %0, t; }" : "=r"(a) : "l"(p));
    return a;
}

#define CP_ASYNC16(saddr, gptr) \
    asm volatile("cp.async.cg.shared.global [%0], [%1], 16;" :: "r"(saddr), "l"(gptr))
#define CP_ASYNC_COMMIT() asm volatile("cp.async.commit_group;" ::: "memory")
#define CP_ASYNC_WAIT1()  asm volatile("cp.async.wait_group 1;" ::: "memory")

__device__ __forceinline__ void ldsm_x4(uint32_t& r0, uint32_t& r1, uint32_t& r2, uint32_t& r3,
                                        uint32_t addr) {
    asm volatile("ldmatrix.sync.aligned.m8n8.x4.shared.b16 {%0,%1,%2,%3}, [%4];"
                 : "=r"(r0), "=r"(r1), "=r"(r2), "=r"(r3) : "r"(addr));
}

__device__ __forceinline__ void mma_16816(float* c, const uint32_t* a, const uint32_t* b) {
    asm volatile(
        "mma.sync.aligned.m16n8k16.row.col.f32.f16.f16.f32 "
        "{%0,%1,%2,%3}, {%4,%5,%6,%7}, {%8,%9}, {%0,%1,%2,%3};"
        : "+f"(c[0]), "+f"(c[1]), "+f"(c[2]), "+f"(c[3])
        : "r"(a[0]), "r"(a[1]), "r"(a[2]), "r"(a[3]), "r"(b[0]), "r"(b[1]));
}

// ===================== conversion kernels =====================
__global__ void __launch_bounds__(256) convert_x_kernel(const float* __restrict__ x, int n4) {
    int i = blockIdx.x * blockDim.x + threadIdx.x;
    if (i >= n4) return;
    float4 v = reinterpret_cast<const float4*>(x)[i];
    __half2 a = __floats2half2_rn(v.x, v.y);
    __half2 b = __floats2half2_rn(v.z, v.w);
    uint2 u;
    u.x = *reinterpret_cast<uint32_t*>(&a);
    u.y = *reinterpret_cast<uint32_t*>(&b);
    reinterpret_cast<uint2*>(g_xh)[i] = u;
}

__global__ void __launch_bounds__(256) convert_w_kernel(const int* __restrict__ w, int n4) {
    int i = blockIdx.x * blockDim.x + threadIdx.x;
    if (i >= n4) return;
    int4 v = reinterpret_cast<const int4*>(w)[i];
    __half2 a = __halves2half2(__int2half_rn(v.x), __int2half_rn(v.y));
    __half2 b = __halves2half2(__int2half_rn(v.z), __int2half_rn(v.w));
    uint2 u;
    u.x = *reinterpret_cast<uint32_t*>(&a);
    u.y = *reinterpret_cast<uint32_t*>(&b);
    reinterpret_cast<uint2*>(g_wh)[i] = u;
}

// ===================== GEMM =====================
// cp.async fill of one stage. A: 128 rows x 8 chunks(16B); B: 256 rows x 8 chunks.
// Swizzle: chunk' = chunk ^ (row & 7); matches the ldmatrix reader below.
__device__ __forceinline__ void load_tile(const __half* __restrict__ gA,
                                          const __half* __restrict__ gB,
                                          uint32_t sA, uint32_t sB, int k0, int tid) {
#pragma unroll
    for (int i = 0; i < 2; i++) {                       // A: 1024 chunks / 512 thr
        int idx = tid + i * THREADS;
        int row = idx >> 3, c = idx & 7;
        const __half* g = gA + (size_t)row * K_DIM + k0 + c * 8;
        uint32_t soff = (uint32_t)(row * 128 + ((c ^ (row & 7)) << 4));
        CP_ASYNC16(sA + soff, g);
    }
#pragma unroll
    for (int i = 0; i < 4; i++) {                       // B: 2048 chunks / 512 thr
        int idx = tid + i * THREADS;
        int row = idx >> 3, c = idx & 7;
        const __half* g = gB + (size_t)row * K_DIM + k0 + c * 8;
        uint32_t soff = (uint32_t)(row * 128 + ((c ^ (row & 7)) << 4));
        CP_ASYNC16(sB + soff, g);
    }
    CP_ASYNC_COMMIT();
}

__global__ void __launch_bounds__(THREADS, 1)
gemm_kernel(const float* __restrict__ scales, const float* __restrict__ bias,
            float* __restrict__ out, int M) {
    extern __shared__ char smem_raw[];
    uint32_t raw = smem_u32(smem_raw);
    uint32_t delta = (128u - (raw & 127u)) & 127u;      // align base to 128B
    char* smem = smem_raw + delta;
    const uint32_t sb = raw + delta;

    const int tid = threadIdx.x;
    const int wid = tid >> 5;
    const int lane = tid & 31;
    const int warp_m = wid & 1;        // 2 M-blocks of 64
    const int warp_n = wid >> 1;       // 8 N-blocks of 32

    // ---- tile rasterization: group 8 n-tiles, sweep all m inside (L2 reuse) ----
    const int tiles_m = M / BM;
    const int tiles_n = N_DIM / BN;
    const int GN = 8;
    int id = blockIdx.x;
    int width = GN * tiles_m;
    int g = id / width, r = id % width;
    int gn = g * GN;
    int gsz = tiles_n - gn < GN ? tiles_n - gn : GN;
    int nt = gn + (r % gsz);
    int mt = r / gsz;
    const int m0 = mt * BM, n0 = nt * BN;

    // ---- scales/bias to smem ----
    float* inv_s = reinterpret_cast<float*>(smem + OFF_INV);
    float* bia_s = reinterpret_cast<float*>(smem + OFF_BIAS);
    for (int i = tid; i < BN; i += THREADS) {
        inv_s[i] = 1.0f / scales[n0 + i];
        bia_s[i] = bias[n0 + i];
    }

    const __half* gA = g_xh + (size_t)m0 * K_DIM;
    const __half* gB = g_wh + (size_t)n0 * K_DIM;

    // ---- prologue: fill STAGES-1 stages ----
#pragma unroll
    for (int t = 0; t < STAGES - 1; t++)
        load_tile(gA, gB, sb + OFF_A + t * A_STAGE_BYTES, sb + OFF_B + t * B_STAGE_BYTES,
                  t * BK, tid);

    // ---- per-lane ldmatrix addressing (swizzle-aware, loop-invariant parts) ----
    const int hi = lane >> 4;                       // selects k-half chunk
    const int rA = warp_m * 64 + (lane & 15);       // A row within tile (ms adds +16k)
    const int rxA = rA & 7;
    const int rB = warp_n * 32 + (lane & 15);       // B row within tile (bs adds +16)
    const int rxB = rB & 7;

    float acc[4][4][4];
#pragma unroll
    for (int i = 0; i < 4; i++)
#pragma unroll
        for (int j = 0; j < 4; j++)
#pragma unroll
            for (int e = 0; e < 4; e++) acc[i][j][e] = 0.0f;

    // ---- main K loop ----
#pragma unroll 1
    for (int t = 0; t < NKT; t++) {
        CP_ASYNC_WAIT1();          // tile t resident (1 newer group may be in flight)
        __syncthreads();

        if (t + STAGES - 1 < NKT) {
            int s = (t + STAGES - 1) % STAGES;
            load_tile(gA, gB, sb + OFF_A + s * A_STAGE_BYTES, sb + OFF_B + s * B_STAGE_BYTES,
                      (t + STAGES - 1) * BK, tid);
        } else {
            CP_ASYNC_COMMIT();     // empty group keeps wait_group invariant
        }

        int slot = t % STAGES;
        uint32_t sA = sb + OFF_A + slot * A_STAGE_BYTES;
        uint32_t sB = sb + OFF_B + slot * B_STAGE_BYTES;

#pragma unroll
        for (int ks = 0; ks < 4; ks++) {
            uint32_t a_frag[4][4];
            uint32_t b_frag[4][2];
#pragma unroll
            for (int ms = 0; ms < 4; ms++) {
                uint32_t addr = sA + (uint32_t)((rA + ms * 16) * 128)
                                   + (uint32_t)((((ks << 1) | hi) ^ rxA) << 4);
                ldsm_x4(a_frag[ms][0], a_frag[ms][1], a_frag[ms][2], a_frag[ms][3], addr);
            }
#pragma unroll
            for (int bs = 0; bs < 2; bs++) {
                uint32_t addr = sB + (uint32_t)((rB + bs * 16) * 128)
                                   + (uint32_t)((((ks << 1) | hi) ^ rxB) << 4);
                uint32_t r0, r1, r2, r3;
                ldsm_x4(r0, r1, r2, r3, addr);
                // matrix0=(n0-7,k0-7)->nstep(2bs).b0, matrix1=(n8-15,k0-7)->nstep(2bs+1).b0
                // matrix2=(n0-7,k8-15)->nstep(2bs).b1, matrix3->nstep(2bs+1).b1
                b_frag[2 * bs + 0][0] = r0;
                b_frag[2 * bs + 1][0] = r1;
                b_frag[2 * bs + 0][1] = r2;
                b_frag[2 * bs + 1][1] = r3;
            }
#pragma unroll
            for (int ms = 0; ms < 4; ms++)
#pragma unroll
                for (int ns = 0; ns < 4; ns++)
                    mma_16816(acc[ms][ns], a_frag[ms], b_frag[ns]);
        }
    }

    // ---- epilogue: scale + bias, float2 stores ----
    const int row_in_warp = lane >> 2;
    const int col_pair = (lane & 3) * 2;
#pragma unroll
    for (int ms = 0; ms < 4; ms++) {
#pragma unroll
        for (int ns = 0; ns < 4; ns++) {
            int cl = warp_n * 32 + ns * 8 + col_pair;   // 0..255
            float i0 = inv_s[cl], i1 = inv_s[cl + 1];
            float b0 = bia_s[cl], b1 = bia_s[cl + 1];
            int row0 = m0 + warp_m * 64 + ms * 16 + row_in_warp;
            float* p0 = out + (size_t)row0 * N_DIM + n0 + cl;
            float* p1 = p0 + (size_t)8 * N_DIM;
            float2 v0, v1;
            v0.x = fmaf(acc[ms][ns][0], i0, b0);
            v0.y = fmaf(acc[ms][ns][1], i1, b1);
            v1.x = fmaf(acc[ms][ns][2], i0, b0);
            v1.y = fmaf(acc[ms][ns][3], i1, b1);
            *reinterpret_cast<float2*>(p0) = v0;
            *reinterpret_cast<float2*>(p1) = v1;
        }
    }
}

// ===================== launch =====================
extern "C" void kernel_launch(void* const* d_in, const int* in_sizes, int n_in,
                              void* d_out, int out_size) {
    const float* x      = (const float*)d_in[0];
    const int*   Wq     = (const int*)d_in[1];
    const float* scales = (const float*)d_in[2];
    const float* bias   = (const float*)d_in[3];
    float*       out    = (float*)d_out;

    int M = in_sizes[0] / K_DIM;   // 8192

    int n4x = (int)(((size_t)M * K_DIM) / 4);
    convert_x_kernel<<<(n4x + 255) / 256, 256>>>(x, n4x);
    int n4w = (int)(((size_t)N_DIM * K_DIM) / 4);
    convert_w_kernel<<<(n4w + 255) / 256, 256>>>(Wq, n4w);

    cudaFuncSetAttribute(gemm_kernel, cudaFuncAttributeMaxDynamicSharedMemorySize, SMEM_ALLOC);

    int grid = (M / BM) * (N_DIM / BN);
    gemm_kernel<<<grid, THREADS, SMEM_ALLOC>>>(scales, bias, out, M);
}

// round 9
// speedup vs baseline: 1.0034x; 1.0034x over previous
#include <cuda_runtime.h>
#include <cuda_fp16.h>
#include <cstdint>

// ===================== problem constants =====================
#define K_DIM 4096
#define N_DIM 16384
#define M_MAX 8192

// ===================== GEMM tiling =====================
#define BM 128
#define BN 256
#define BK 64                      // fp16 elems = 128 bytes = one swizzled row
#define STAGES 4
#define NKT (K_DIM / BK)           // 64
#define THREADS 256                // 8 warps: 2 (M) x 4 (N), warp tile 64x64

#define A_STAGE_BYTES (BM * 128)   // 16384
#define B_STAGE_BYTES (BN * 128)   // 32768

// shared memory layout (relative to 128B-aligned base)
#define OFF_INV  0                 // BN floats
#define OFF_BIAS (BN * 4)          // BN floats
#define OFF_A    (2 * BN * 4)      // 2048, 128B aligned
#define OFF_B    (OFF_A + STAGES * A_STAGE_BYTES)
#define SMEM_USE (OFF_B + STAGES * B_STAGE_BYTES)   // ~198.7 KB
#define SMEM_ALLOC (SMEM_USE + 256)

// fp16 scratch (conversion targets) — __device__ globals per allocation rules
__device__ __align__(16) __half g_xh[(size_t)M_MAX * K_DIM];
__device__ __align__(16) __half g_wh[(size_t)N_DIM * K_DIM];

// ===================== PTX helpers =====================
__device__ __forceinline__ uint32_t smem_u32(const void* p) {
    uint32_t a;
    asm("{ .reg .u64 t; cvta.to.shared.u64 t, %1; cvt.u32.u64 %0, t; }" : "=r"(a) : "l"(p));
    return a;
}

#define CP_ASYNC16(saddr, gptr) \
    asm volatile("cp.async.cg.shared.global [%0], [%1], 16;" :: "r"(saddr), "l"(gptr))
#define CP_ASYNC_COMMIT() asm volatile("cp.async.commit_group;" ::: "memory")
#define CP_ASYNC_WAIT2()  asm volatile("cp.async.wait_group 2;" ::: "memory")

__device__ __forceinline__ void ldsm_x4(uint32_t& r0, uint32_t& r1, uint32_t& r2, uint32_t& r3,
                                        uint32_t addr) {
    asm volatile("ldmatrix.sync.aligned.m8n8.x4.shared.b16 {%0,%1,%2,%3}, [%4];"
                 : "=r"(r0), "=r"(r1), "=r"(r2), "=r"(r3) : "r"(addr));
}

__device__ __forceinline__ void mma_16816(float* c, const uint32_t* a, const uint32_t* b) {
    asm volatile(
        "mma.sync.aligned.m16n8k16.row.col.f32.f16.f16.f32 "
        "{%0,%1,%2,%3}, {%4,%5,%6,%7}, {%8,%9}, {%0,%1,%2,%3};"
        : "+f"(c[0]), "+f"(c[1]), "+f"(c[2]), "+f"(c[3])
        : "r"(a[0]), "r"(a[1]), "r"(a[2]), "r"(a[3]), "r"(b[0]), "r"(b[1]));
}

// ===================== conversion kernels =====================
__global__ void __launch_bounds__(256) convert_x_kernel(const float* __restrict__ x, int n4) {
    int i = blockIdx.x * blockDim.x + threadIdx.x;
    if (i >= n4) return;
    float4 v = reinterpret_cast<const float4*>(x)[i];
    __half2 a = __floats2half2_rn(v.x, v.y);
    __half2 b = __floats2half2_rn(v.z, v.w);
    uint2 u;
    u.x = *reinterpret_cast<uint32_t*>(&a);
    u.y = *reinterpret_cast<uint32_t*>(&b);
    reinterpret_cast<uint2*>(g_xh)[i] = u;
}

__global__ void __launch_bounds__(256) convert_w_kernel(const int* __restrict__ w, int n4) {
    int i = blockIdx.x * blockDim.x + threadIdx.x;
    if (i >= n4) return;
    int4 v = reinterpret_cast<const int4*>(w)[i];
    __half2 a = __halves2half2(__int2half_rn(v.x), __int2half_rn(v.y));
    __half2 b = __halves2half2(__int2half_rn(v.z), __int2half_rn(v.w));
    uint2 u;
    u.x = *reinterpret_cast<uint32_t*>(&a);
    u.y = *reinterpret_cast<uint32_t*>(&b);
    reinterpret_cast<uint2*>(g_wh)[i] = u;
}

// ===================== GEMM =====================
// cp.async fill of one stage. A: 128 rows x 8 chunks(16B); B: 256 rows x 8 chunks.
// Swizzle: chunk' = chunk ^ (row & 7); matches the ldmatrix reader below.
__device__ __forceinline__ void load_tile(const __half* __restrict__ gA,
                                          const __half* __restrict__ gB,
                                          uint32_t sA, uint32_t sB, int k0, int tid) {
#pragma unroll
    for (int i = 0; i < 4; i++) {                       // A: 1024 chunks / 256 thr
        int idx = tid + i * THREADS;
        int row = idx >> 3, c = idx & 7;
        const __half* g = gA + (size_t)row * K_DIM + k0 + c * 8;
        uint32_t soff = (uint32_t)(row * 128 + ((c ^ (row & 7)) << 4));
        CP_ASYNC16(sA + soff, g);
    }
#pragma unroll
    for (int i = 0; i < 8; i++) {                       // B: 2048 chunks / 256 thr
        int idx = tid + i * THREADS;
        int row = idx >> 3, c = idx & 7;
        const __half* g = gB + (size_t)row * K_DIM + k0 + c * 8;
        uint32_t soff = (uint32_t)(row * 128 + ((c ^ (row & 7)) << 4));
        CP_ASYNC16(sB + soff, g);
    }
    CP_ASYNC_COMMIT();
}

__global__ void __launch_bounds__(THREADS, 1)
gemm_kernel(const float* __restrict__ scales, const float* __restrict__ bias,
            float* __restrict__ out, int M) {
    extern __shared__ char smem_raw[];
    uint32_t raw = smem_u32(smem_raw);
    uint32_t delta = (128u - (raw & 127u)) & 127u;      // align base to 128B
    char* smem = smem_raw + delta;
    const uint32_t sb = raw + delta;

    const int tid = threadIdx.x;
    const int wid = tid >> 5;
    const int lane = tid & 31;
    const int warp_m = wid & 1;        // 2 M-blocks of 64
    const int warp_n = wid >> 1;       // 4 N-blocks of 64

    // ---- tile rasterization: group 8 n-tiles, sweep all m inside (L2 reuse) ----
    const int tiles_m = M / BM;
    const int tiles_n = N_DIM / BN;
    const int GN = 8;
    int id = blockIdx.x;
    int width = GN * tiles_m;
    int g = id / width, r = id % width;
    int gn = g * GN;
    int gsz = tiles_n - gn < GN ? tiles_n - gn : GN;
    int nt = gn + (r % gsz);
    int mt = r / gsz;
    const int m0 = mt * BM, n0 = nt * BN;

    // ---- scales/bias to smem ----
    float* inv_s = reinterpret_cast<float*>(smem + OFF_INV);
    float* bia_s = reinterpret_cast<float*>(smem + OFF_BIAS);
    for (int i = tid; i < BN; i += THREADS) {
        inv_s[i] = 1.0f / scales[n0 + i];
        bia_s[i] = bias[n0 + i];
    }

    const __half* gA = g_xh + (size_t)m0 * K_DIM;
    const __half* gB = g_wh + (size_t)n0 * K_DIM;

    // ---- prologue: fill STAGES-1 stages ----
#pragma unroll
    for (int t = 0; t < STAGES - 1; t++)
        load_tile(gA, gB, sb + OFF_A + t * A_STAGE_BYTES, sb + OFF_B + t * B_STAGE_BYTES,
                  t * BK, tid);

    // ---- per-lane ldmatrix addressing (swizzle-aware, loop-invariant parts) ----
    const int hi = lane >> 4;                       // selects k-half chunk
    const int rA = warp_m * 64 + (lane & 15);       // A row within tile (ms adds +16)
    const int rxA = rA & 7;
    const int rB = warp_n * 64 + (lane & 15);       // B row within tile (bs adds +16)
    const int rxB = rB & 7;

    float acc[4][8][4];
#pragma unroll
    for (int i = 0; i < 4; i++)
#pragma unroll
        for (int j = 0; j < 8; j++)
#pragma unroll
            for (int e = 0; e < 4; e++) acc[i][j][e] = 0.0f;

    // ---- main K loop ----
#pragma unroll 1
    for (int t = 0; t < NKT; t++) {
        CP_ASYNC_WAIT2();          // tile t resident (2 newer groups may be in flight)
        __syncthreads();

        if (t + STAGES - 1 < NKT) {
            int s = (t + STAGES - 1) % STAGES;
            load_tile(gA, gB, sb + OFF_A + s * A_STAGE_BYTES, sb + OFF_B + s * B_STAGE_BYTES,
                      (t + STAGES - 1) * BK, tid);
        } else {
            CP_ASYNC_COMMIT();     // empty group keeps wait_group invariant
        }

        int slot = t % STAGES;
        uint32_t sA = sb + OFF_A + slot * A_STAGE_BYTES;
        uint32_t sB = sb + OFF_B + slot * B_STAGE_BYTES;

#pragma unroll
        for (int ks = 0; ks < 4; ks++) {
            uint32_t a_frag[4][4];
            uint32_t b_frag[8][2];
#pragma unroll
            for (int ms = 0; ms < 4; ms++) {
                uint32_t addr = sA + (uint32_t)((rA + ms * 16) * 128)
                                   + (uint32_t)((((ks << 1) | hi) ^ rxA) << 4);
                ldsm_x4(a_frag[ms][0], a_frag[ms][1], a_frag[ms][2], a_frag[ms][3], addr);
            }
#pragma unroll
            for (int bs = 0; bs < 4; bs++) {
                uint32_t addr = sB + (uint32_t)((rB + bs * 16) * 128)
                                   + (uint32_t)((((ks << 1) | hi) ^ rxB) << 4);
                uint32_t r0, r1, r2, r3;
                ldsm_x4(r0, r1, r2, r3, addr);
                b_frag[2 * bs + 0][0] = r0;
                b_frag[2 * bs + 1][0] = r1;
                b_frag[2 * bs + 0][1] = r2;
                b_frag[2 * bs + 1][1] = r3;
            }
#pragma unroll
            for (int ms = 0; ms < 4; ms++)
#pragma unroll
                for (int ns = 0; ns < 8; ns++)
                    mma_16816(acc[ms][ns], a_frag[ms], b_frag[ns]);
        }
    }

    // ---- epilogue: scale + bias, float2 stores ----
    const int row_in_warp = lane >> 2;
    const int col_pair = (lane & 3) * 2;
#pragma unroll
    for (int ms = 0; ms < 4; ms++) {
#pragma unroll
        for (int ns = 0; ns < 8; ns++) {
            int cl = warp_n * 64 + ns * 8 + col_pair;   // 0..255
            float i0 = inv_s[cl], i1 = inv_s[cl + 1];
            float b0 = bia_s[cl], b1 = bia_s[cl + 1];
            int row0 = m0 + warp_m * 64 + ms * 16 + row_in_warp;
            float* p0 = out + (size_t)row0 * N_DIM + n0 + cl;
            float* p1 = p0 + (size_t)8 * N_DIM;
            float2 v0, v1;
            v0.x = fmaf(acc[ms][ns][0], i0, b0);
            v0.y = fmaf(acc[ms][ns][1], i1, b1);
            v1.x = fmaf(acc[ms][ns][2], i0, b0);
            v1.y = fmaf(acc[ms][ns][3], i1, b1);
            *reinterpret_cast<float2*>(p0) = v0;
            *reinterpret_cast<float2*>(p1) = v1;
        }
    }
}

// ===================== launch =====================
extern "C" void kernel_launch(void* const* d_in, const int* in_sizes, int n_in,
                              void* d_out, int out_size) {
    const float* x      = (const float*)d_in[0];
    const int*   Wq     = (const int*)d_in[1];
    const float* scales = (const float*)d_in[2];
    const float* bias   = (const float*)d_in[3];
    float*       out    = (float*)d_out;

    int M = in_sizes[0] / K_DIM;   // 8192

    int n4x = (int)(((size_t)M * K_DIM) / 4);
    convert_x_kernel<<<(n4x + 255) / 256, 256>>>(x, n4x);
    int n4w = (int)(((size_t)N_DIM * K_DIM) / 4);
    convert_w_kernel<<<(n4w + 255) / 256, 256>>>(Wq, n4w);

    cudaFuncSetAttribute(gemm_kernel, cudaFuncAttributeMaxDynamicSharedMemorySize, SMEM_ALLOC);

    int grid = (M / BM) * (N_DIM / BN);
    gemm_kernel<<<grid, THREADS, SMEM_ALLOC>>>(scales, bias, out, M);
}

// round 10
// speedup vs baseline: 1.0055x; 1.0021x over previous
#include <cuda_runtime.h>
#include <cuda_fp16.h>
#include <cstdint>

// ===================== problem constants =====================
#define K_DIM 4096
#define N_DIM 16384
#define M_MAX 8192

// ===================== GEMM tiling =====================
#define BM 128
#define BN 256
#define BK 64                      // fp16 elems = 128 bytes = one swizzled row
#define STAGES 4
#define NKT (K_DIM / BK)           // 64
#define THREADS 256                // 8 warps: 2 (M) x 4 (N), warp tile 64x64

#define A_STAGE_BYTES (BM * 128)   // 16384
#define B_STAGE_BYTES (BN * 128)   // 32768

// shared memory layout (relative to 128B-aligned base)
#define OFF_INV  0                 // BN floats
#define OFF_BIAS (BN * 4)          // BN floats
#define OFF_A    (2 * BN * 4)      // 2048, 128B aligned
#define OFF_B    (OFF_A + STAGES * A_STAGE_BYTES)
#define SMEM_USE (OFF_B + STAGES * B_STAGE_BYTES)   // ~198.7 KB
#define SMEM_ALLOC (SMEM_USE + 256)

// fp16 scratch (conversion targets) — __device__ globals per allocation rules
__device__ __align__(16) __half g_xh[(size_t)M_MAX * K_DIM];
__device__ __align__(16) __half g_wh[(size_t)N_DIM * K_DIM];

// ===================== PTX helpers =====================
__device__ __forceinline__ uint32_t smem_u32(const void* p) {
    uint32_t a;
    asm("{ .reg .u64 t; cvta.to.shared.u64 t, %1; cvt.u32.u64 %0, t; }" : "=r"(a) : "l"(p));
    return a;
}

#define CP_ASYNC16(saddr, gptr) \
    asm volatile("cp.async.cg.shared.global [%0], [%1], 16;" :: "r"(saddr), "l"(gptr))
#define CP_ASYNC_COMMIT() asm volatile("cp.async.commit_group;" ::: "memory")
#define CP_ASYNC_WAIT2()  asm volatile("cp.async.wait_group 2;" ::: "memory")

__device__ __forceinline__ void ldsm_x4(uint32_t& r0, uint32_t& r1, uint32_t& r2, uint32_t& r3,
                                        uint32_t addr) {
    asm volatile("ldmatrix.sync.aligned.m8n8.x4.shared.b16 {%0,%1,%2,%3}, [%4];"
                 : "=r"(r0), "=r"(r1), "=r"(r2), "=r"(r3) : "r"(addr));
}

__device__ __forceinline__ void mma_16816(float* c, const uint32_t* a, const uint32_t* b) {
    asm volatile(
        "mma.sync.aligned.m16n8k16.row.col.f32.f16.f16.f32 "
        "{%0,%1,%2,%3}, {%4,%5,%6,%7}, {%8,%9}, {%0,%1,%2,%3};"
        : "+f"(c[0]), "+f"(c[1]), "+f"(c[2]), "+f"(c[3])
        : "r"(a[0]), "r"(a[1]), "r"(a[2]), "r"(a[3]), "r"(b[0]), "r"(b[1]));
}

// ===================== conversion kernels =====================
__global__ void __launch_bounds__(256) convert_x_kernel(const float* __restrict__ x, int n4) {
    int i = blockIdx.x * blockDim.x + threadIdx.x;
    if (i >= n4) return;
    float4 v = reinterpret_cast<const float4*>(x)[i];
    __half2 a = __floats2half2_rn(v.x, v.y);
    __half2 b = __floats2half2_rn(v.z, v.w);
    uint2 u;
    u.x = *reinterpret_cast<uint32_t*>(&a);
    u.y = *reinterpret_cast<uint32_t*>(&b);
    reinterpret_cast<uint2*>(g_xh)[i] = u;
}

__global__ void __launch_bounds__(256) convert_w_kernel(const int* __restrict__ w, int n4) {
    int i = blockIdx.x * blockDim.x + threadIdx.x;
    if (i >= n4) return;
    int4 v = reinterpret_cast<const int4*>(w)[i];
    __half2 a = __halves2half2(__int2half_rn(v.x), __int2half_rn(v.y));
    __half2 b = __halves2half2(__int2half_rn(v.z), __int2half_rn(v.w));
    uint2 u;
    u.x = *reinterpret_cast<uint32_t*>(&a);
    u.y = *reinterpret_cast<uint32_t*>(&b);
    reinterpret_cast<uint2*>(g_wh)[i] = u;
}

// ===================== GEMM =====================
// cp.async fill of one stage. A: 128 rows x 8 chunks(16B); B: 256 rows x 8 chunks.
// Swizzle: chunk' = chunk ^ (row & 7); matches the ldmatrix reader below.
__device__ __forceinline__ void load_tile(const __half* __restrict__ gA,
                                          const __half* __restrict__ gB,
                                          uint32_t sA, uint32_t sB, int k0, int tid) {
#pragma unroll
    for (int i = 0; i < 4; i++) {                       // A: 1024 chunks / 256 thr
        int idx = tid + i * THREADS;
        int row = idx >> 3, c = idx & 7;
        const __half* g = gA + (size_t)row * K_DIM + k0 + c * 8;
        uint32_t soff = (uint32_t)(row * 128 + ((c ^ (row & 7)) << 4));
        CP_ASYNC16(sA + soff, g);
    }
#pragma unroll
    for (int i = 0; i < 8; i++) {                       // B: 2048 chunks / 256 thr
        int idx = tid + i * THREADS;
        int row = idx >> 3, c = idx & 7;
        const __half* g = gB + (size_t)row * K_DIM + k0 + c * 8;
        uint32_t soff = (uint32_t)(row * 128 + ((c ^ (row & 7)) << 4));
        CP_ASYNC16(sB + soff, g);
    }
    CP_ASYNC_COMMIT();
}

__global__ void __launch_bounds__(THREADS, 1)
gemm_kernel(const float* __restrict__ scales, const float* __restrict__ bias,
            float* __restrict__ out, int M) {
    extern __shared__ char smem_raw[];
    uint32_t raw = smem_u32(smem_raw);
    uint32_t delta = (128u - (raw & 127u)) & 127u;      // align base to 128B
    char* smem = smem_raw + delta;
    const uint32_t sb = raw + delta;

    const int tid = threadIdx.x;
    const int wid = tid >> 5;
    const int lane = tid & 31;
    const int warp_m = wid & 1;        // 2 M-blocks of 64
    const int warp_n = wid >> 1;       // 4 N-blocks of 64

    // ---- tile rasterization: group 8 n-tiles, sweep all m inside (L2 reuse) ----
    const int tiles_m = M / BM;
    const int tiles_n = N_DIM / BN;
    const int GN = 8;
    int id = blockIdx.x;
    int width = GN * tiles_m;
    int g = id / width, r = id % width;
    int gn = g * GN;
    int gsz = tiles_n - gn < GN ? tiles_n - gn : GN;
    int nt = gn + (r % gsz);
    int mt = r / gsz;
    const int m0 = mt * BM, n0 = nt * BN;

    // ---- scales/bias to smem ----
    float* inv_s = reinterpret_cast<float*>(smem + OFF_INV);
    float* bia_s = reinterpret_cast<float*>(smem + OFF_BIAS);
    for (int i = tid; i < BN; i += THREADS) {
        inv_s[i] = 1.0f / scales[n0 + i];
        bia_s[i] = bias[n0 + i];
    }

    const __half* gA = g_xh + (size_t)m0 * K_DIM;
    const __half* gB = g_wh + (size_t)n0 * K_DIM;

    // ---- prologue: fill STAGES-1 stages ----
#pragma unroll
    for (int t = 0; t < STAGES - 1; t++)
        load_tile(gA, gB, sb + OFF_A + t * A_STAGE_BYTES, sb + OFF_B + t * B_STAGE_BYTES,
                  t * BK, tid);

    // ---- per-lane ldmatrix addressing (swizzle-aware, loop-invariant parts) ----
    const int hi = lane >> 4;                       // selects k-half chunk
    const int rA = warp_m * 64 + (lane & 15);       // A row within tile (ms adds +16)
    const int rxA = rA & 7;
    const int rB = warp_n * 64 + (lane & 15);       // B row within tile (bs adds +16)
    const int rxB = rB & 7;

    float acc[4][8][4];
#pragma unroll
    for (int i = 0; i < 4; i++)
#pragma unroll
        for (int j = 0; j < 8; j++)
#pragma unroll
            for (int e = 0; e < 4; e++) acc[i][j][e] = 0.0f;

    // ---- main K loop ----
#pragma unroll 1
    for (int t = 0; t < NKT; t++) {
        CP_ASYNC_WAIT2();          // tile t resident (2 newer groups may be in flight)
        __syncthreads();

        if (t + STAGES - 1 < NKT) {
            int s = (t + STAGES - 1) % STAGES;
            load_tile(gA, gB, sb + OFF_A + s * A_STAGE_BYTES, sb + OFF_B + s * B_STAGE_BYTES,
                      (t + STAGES - 1) * BK, tid);
        } else {
            CP_ASYNC_COMMIT();     // empty group keeps wait_group invariant
        }

        int slot = t % STAGES;
        uint32_t sA = sb + OFF_A + slot * A_STAGE_BYTES;
        uint32_t sB = sb + OFF_B + slot * B_STAGE_BYTES;

#pragma unroll
        for (int ks = 0; ks < 4; ks++) {
            uint32_t a_frag[4][4];
            uint32_t b_frag[8][2];
#pragma unroll
            for (int ms = 0; ms < 4; ms++) {
                uint32_t addr = sA + (uint32_t)((rA + ms * 16) * 128)
                                   + (uint32_t)((((ks << 1) | hi) ^ rxA) << 4);
                ldsm_x4(a_frag[ms][0], a_frag[ms][1], a_frag[ms][2], a_frag[ms][3], addr);
            }
#pragma unroll
            for (int bs = 0; bs < 4; bs++) {
                uint32_t addr = sB + (uint32_t)((rB + bs * 16) * 128)
                                   + (uint32_t)((((ks << 1) | hi) ^ rxB) << 4);
                uint32_t r0, r1, r2, r3;
                ldsm_x4(r0, r1, r2, r3, addr);
                b_frag[2 * bs + 0][0] = r0;
                b_frag[2 * bs + 1][0] = r1;
                b_frag[2 * bs + 0][1] = r2;
                b_frag[2 * bs + 1][1] = r3;
            }
#pragma unroll
            for (int ms = 0; ms < 4; ms++)
#pragma unroll
                for (int ns = 0; ns < 8; ns++)
                    mma_16816(acc[ms][ns], a_frag[ms], b_frag[ns]);
        }
    }

    // ---- epilogue: scale + bias, float2 stores ----
    const int row_in_warp = lane >> 2;
    const int col_pair = (lane & 3) * 2;
#pragma unroll
    for (int ms = 0; ms < 4; ms++) {
#pragma unroll
        for (int ns = 0; ns < 8; ns++) {
            int cl = warp_n * 64 + ns * 8 + col_pair;   // 0..255
            float i0 = inv_s[cl], i1 = inv_s[cl + 1];
            float b0 = bia_s[cl], b1 = bia_s[cl + 1];
            int row0 = m0 + warp_m * 64 + ms * 16 + row_in_warp;
            float* p0 = out + (size_t)row0 * N_DIM + n0 + cl;
            float* p1 = p0 + (size_t)8 * N_DIM;
            float2 v0, v1;
            v0.x = fmaf(acc[ms][ns][0], i0, b0);
            v0.y = fmaf(acc[ms][ns][1], i1, b1);
            v1.x = fmaf(acc[ms][ns][2], i0, b0);
            v1.y = fmaf(acc[ms][ns][3], i1, b1);
            *reinterpret_cast<float2*>(p0) = v0;
            *reinterpret_cast<float2*>(p1) = v1;
        }
    }
}

// ===================== launch =====================
extern "C" void kernel_launch(void* const* d_in, const int* in_sizes, int n_in,
                              void* d_out, int out_size) {
    const float* x      = (const float*)d_in[0];
    const int*   Wq     = (const int*)d_in[1];
    const float* scales = (const float*)d_in[2];
    const float* bias   = (const float*)d_in[3];
    float*       out    = (float*)d_out;

    int M = in_sizes[0] / K_DIM;   // 8192

    int n4x = (int)(((size_t)M * K_DIM) / 4);
    convert_x_kernel<<<(n4x + 255) / 256, 256>>>(x, n4x);
    int n4w = (int)(((size_t)N_DIM * K_DIM) / 4);
    convert_w_kernel<<<(n4w + 255) / 256, 256>>>(Wq, n4w);

    cudaFuncSetAttribute(gemm_kernel, cudaFuncAttributeMaxDynamicSharedMemorySize, SMEM_ALLOC);

    int grid = (M / BM) * (N_DIM / BN);
    gemm_kernel<<<grid, THREADS, SMEM_ALLOC>>>(scales, bias, out, M);
}